// round 9
// baseline (speedup 1.0000x reference)
#include <cuda_runtime.h>

#define NB    2048
#define GRID  (NB / 2)
#define KD    256
#define PD    256
#define SD    10
#define PADS  12          // xst row stride in floats (10 used + 2 pad)
#define LAMB  0.5f
#define EPSF  1e-9f
#define NEG_PAD -1e30f

#define STAGES     4
#define PRE        3
#define ROWS_PER_STAGE 8
#define NSTAGE_IT  (KD / ROWS_PER_STAGE)     // 32
#define STAGE_FLOATS (ROWS_PER_STAGE * PD)   // 2048

// dynamic smem layout (floats):
//   pbuf : [0, 16384)            2 halves x 4 stages x 2048
//   xst  : [16384, 22528)        2 halves x 256*12
//   cmag : [22528, 27648)        2 halves x 10*256
#define OFF_PBUF  0
#define OFF_XST   16384
#define OFF_CMAG  22528
#define DSM_FLOATS 27648
#define DSM_BYTES  (DSM_FLOATS * 4)

__device__ float    g_logmse[NB];
__device__ float    g_pen[NB];
__device__ unsigned g_done = 0;

typedef unsigned long long ull;

__device__ __forceinline__ ull ffma2(ull a, ull b, ull c) {
    ull d;
    asm("fma.rn.f32x2 %0, %1, %2, %3;" : "=l"(d) : "l"(a), "l"(b), "l"(c));
    return d;
}
__device__ __forceinline__ ull pack2(float x) {
    unsigned u = __float_as_uint(x);
    ull d;
    asm("mov.b64 %0, {%1, %2};" : "=l"(d) : "r"(u), "r"(u));
    return d;
}
__device__ __forceinline__ void unpack2(ull a, float& lo, float& hi) {
    unsigned l, h;
    asm("mov.b64 {%0, %1}, %2;" : "=r"(l), "=r"(h) : "l"(a));
    lo = __uint_as_float(l);
    hi = __uint_as_float(h);
}
__device__ __forceinline__ void cp_async16(unsigned dst_smem, const void* src) {
    asm volatile("cp.async.cg.shared.global [%0], [%1], 16;\n"
                 :: "r"(dst_smem), "l"(src));
}
__device__ __forceinline__ void cp_commit() {
    asm volatile("cp.async.commit_group;\n");
}
__device__ __forceinline__ void cp_wait2() {
    asm volatile("cp.async.wait_group 2;\n");
}

__global__ __launch_bounds__(256, 2)
void vil_main_kernel(const float* __restrict__ y_pred,
                     const float* __restrict__ y_true,
                     const float* __restrict__ Pmat,
                     const float* __restrict__ params,
                     const float* __restrict__ Xs,
                     float* __restrict__ out,
                     int out_size)
{
    extern __shared__ __align__(16) float dsm[];
    __shared__ float warr[2][4];
    __shared__ unsigned is_last;

    const int tid  = threadIdx.x;
    const int half = tid >> 7;          // which batch of the pair
    const int ltid = tid & 127;         // thread within half
    const int lane = tid & 31;
    const int wl   = ltid >> 5;         // warp within half: 0..3

    const int b = (blockIdx.x << 1) | half;

    int n = (int)params[b * 3 + 0];
    int k = (int)params[b * 3 + 1];
    int m = (int)params[b * 3 + 2];
    if (k > KD) k = KD;
    int pv = n - k;
    if (pv < 0) pv = 0;
    if (pv > PD) pv = PD;
    if (m < 0) m = 0;
    if (m > 8) m = 8;

    float* pbufh = dsm + OFF_PBUF + half * (STAGES * STAGE_FLOATS);
    float* xh    = dsm + OFF_XST  + half * (KD * PADS);
    float* cmagh = dsm + OFF_CMAG + half * (SD * PD);

    const float* PbBase = Pmat + (size_t)b * KD * PD;

    // ---- per-thread cp.async chunk assignment (4 chunks of 16B per stage) ----
    // chunk id = j*128 + ltid, row = id>>6, coloff = (id&63)*4
    int ch_row[4], ch_col[4];
    unsigned ch_dst[4];
    bool ch_ok[4];
#pragma unroll
    for (int j = 0; j < 4; ++j) {
        int id = j * 128 + ltid;
        ch_row[j] = id >> 6;
        ch_col[j] = (id & 63) * 4;
        ch_ok[j]  = ch_col[j] < pv;      // skip fully-masked chunks
        ch_dst[j] = (unsigned)__cvta_generic_to_shared(
            pbufh + ch_row[j] * PD + ch_col[j]);
    }

    // ---- prologue: issue PRE stages of P while we stage X ----
#pragma unroll
    for (int st = 0; st < PRE; ++st) {
        unsigned soff = (unsigned)(st * STAGE_FLOATS * 4);
#pragma unroll
        for (int j = 0; j < 4; ++j) {
            if (ch_ok[j])
                cp_async16(ch_dst[j] + soff,
                           PbBase + (st * ROWS_PER_STAGE + ch_row[j]) * PD + ch_col[j]);
        }
        cp_commit();
    }

    // ---- stage X transposed + masked into smem (per half) ----
    const float* Xb = Xs + (size_t)b * SD * KD;
    for (int i = ltid; i < SD * KD; i += 128) {
        int s  = i >> 8;          // KD = 256
        int kk = i & (KD - 1);
        float v = Xb[i];
        xh[kk * PADS + s] = (kk < k) ? v : 0.0f;
    }

    // ---- GEMM mainloop over 32 stages of 8 k-rows ----
    const int c0 = ltid << 1;
    const bool active = c0 < pv;

    ull a0 = 0ull, a1 = 0ull, a2 = 0ull, a3 = 0ull, a4 = 0ull;  // column c0
    ull b0 = 0ull, b1 = 0ull, b2 = 0ull, b3 = 0ull, b4 = 0ull;  // column c0+1

    for (int it = 0; it < NSTAGE_IT; ++it) {
        cp_wait2();              // stage `it` resident
        __syncthreads();         // all threads see it; all done with stage it-1

        // issue stage it+PRE (overwrites buffer (it-1)%4 — safe after the sync)
        if (it + PRE < NSTAGE_IT) {
            unsigned soff = (unsigned)(((it + PRE) & (STAGES - 1)) * STAGE_FLOATS * 4);
            const float* src0 = PbBase + (it + PRE) * ROWS_PER_STAGE * PD;
#pragma unroll
            for (int j = 0; j < 4; ++j) {
                if (ch_ok[j])
                    cp_async16(ch_dst[j] + soff, src0 + ch_row[j] * PD + ch_col[j]);
            }
        }
        cp_commit();             // commit every iteration keeps wait_group aligned

        if (active) {
            const float* ps = pbufh + (it & (STAGES - 1)) * STAGE_FLOATS + c0;
            const float* xr = xh + it * ROWS_PER_STAGE * PADS;
#pragma unroll
            for (int r = 0; r < ROWS_PER_STAGE; ++r) {
                const float2 pc = *reinterpret_cast<const float2*>(ps + r * PD);
                const float* row = xr + r * PADS;
                ulonglong2 q0 = *reinterpret_cast<const ulonglong2*>(row);      // s0..s3
                ulonglong2 q1 = *reinterpret_cast<const ulonglong2*>(row + 4);  // s4..s7
                ull x89       = *reinterpret_cast<const ull*>(row + 8);         // s8,s9
                ull pp0 = pack2(pc.x);
                ull pp1 = pack2(pc.y);
                a0 = ffma2(q0.x, pp0, a0);  b0 = ffma2(q0.x, pp1, b0);
                a1 = ffma2(q0.y, pp0, a1);  b1 = ffma2(q0.y, pp1, b1);
                a2 = ffma2(q1.x, pp0, a2);  b2 = ffma2(q1.x, pp1, b2);
                a3 = ffma2(q1.y, pp0, a3);  b3 = ffma2(q1.y, pp1, b3);
                a4 = ffma2(x89,  pp0, a4);  b4 = ffma2(x89,  pp1, b4);
            }
        }
    }
    __syncthreads();   // everyone done reading last stage before cmag reuse phase

    // ---- write masked |C| for both columns ----
    {
        float ca[SD], cb[SD];
        unpack2(a0, ca[0], ca[1]);  unpack2(b0, cb[0], cb[1]);
        unpack2(a1, ca[2], ca[3]);  unpack2(b1, cb[2], cb[3]);
        unpack2(a2, ca[4], ca[5]);  unpack2(b2, cb[4], cb[5]);
        unpack2(a3, ca[6], ca[7]);  unpack2(b3, cb[6], cb[7]);
        unpack2(a4, ca[8], ca[9]);  unpack2(b4, cb[8], cb[9]);
        const bool ok0 = c0 < pv;
        const bool ok1 = (c0 + 1) < pv;
#pragma unroll
        for (int s = 0; s < SD; ++s) {
            float2 w;
            w.x = ok0 ? fabsf(ca[s]) : -1.0f;
            w.y = ok1 ? fabsf(cb[s]) : -1.0f;
            *reinterpret_cast<float2*>(cmagh + s * PD + c0) = w;
        }
    }
    __syncthreads();

    // ---- selection: 4 warps per half, warp wl takes s = wl, wl+4, wl+8 ----
    const int jmax = (pv + 31) >> 5;    // only scan columns < pv (rest are -1)
    float s_hm = 0.0f;
    for (int s = wl; s < SD; s += 4) {
        float t[9];
#pragma unroll
        for (int i = 0; i < 9; ++i) t[i] = NEG_PAD;

        // candidates from X part
#pragma unroll
        for (int j = 0; j < 8; ++j) {
            int kk = lane + 32 * j;
            float v = (kk < k) ? fabsf(xh[kk * PADS + s]) : -1.0f;
#pragma unroll
            for (int i = 8; i >= 1; --i) t[i] = fmaxf(t[i], fminf(t[i - 1], v));
            t[0] = fmaxf(t[0], v);
        }
        // candidates from X@P part, trimmed to valid columns
        for (int j = 0; j < jmax; ++j) {
            float v = cmagh[s * PD + lane + 32 * j];
#pragma unroll
            for (int i = 8; i >= 1; --i) t[i] = fmaxf(t[i], fminf(t[i - 1], v));
            t[0] = fmaxf(t[0], v);
        }

        // butterfly merge of sorted top-9 lists across 32 lanes
#pragma unroll
        for (int st = 0; st < 5; ++st) {
            float r[9], o[9];
#pragma unroll
            for (int i = 0; i < 9; ++i)
                r[i] = __shfl_xor_sync(0xffffffffu, t[i], 1 << st);
#pragma unroll
            for (int j = 0; j < 9; ++j) {
                float mx = fmaxf(t[j], r[j]);
#pragma unroll
                for (int i = 0; i < j; ++i)
                    mx = fmaxf(mx, fminf(t[i], r[j - 1 - i]));
                o[j] = mx;
            }
#pragma unroll
            for (int i = 0; i < 9; ++i) t[i] = o[i];
        }

        float topm = t[0];
#pragma unroll
        for (int i = 1; i < 9; ++i)
            if (m == i) topm = t[i];

        s_hm = fmaxf(s_hm, t[0] / (topm + EPSF));
    }
    if (lane == 0) warr[half][wl] = s_hm;
    __syncthreads();

    // ---- per-batch scalar outputs (one writer per half) ----
    if (ltid == 0) {
        float mh = fmaxf(fmaxf(warr[half][0], warr[half][1]),
                         fmaxf(warr[half][2], warr[half][3]));
        float yp = y_pred[b];
        float lt = log2f(fmaxf(y_true[b], EPSF));
        float lp = log2f(fmaxf(yp, EPSF));
        float d  = lt - lp;
        g_logmse[b] = d * d;
        bool valid  = (m + 1) <= n;
        g_pen[b]    = valid ? fmaxf(mh - yp, 0.0f) : 0.0f;
        __threadfence();
    }
    __syncthreads();

    if (tid == 0) {
        unsigned prev = atomicAdd(&g_done, 1u);
        is_last = (prev == GRID - 1) ? 1u : 0u;
    }
    __syncthreads();

    // ---- last block performs the deterministic final reduction ----
    if (is_last) {
        __threadfence();   // acquire: make all blocks' g_ writes visible
        float* sm1 = dsm;         // reuse dynamic smem (GEMM buffers dead here)
        float* sm2 = dsm + 256;
        float s1 = 0.0f, s2 = 0.0f;
        for (int i = tid; i < NB; i += 256) {   // fixed order -> deterministic
            s1 += g_logmse[i];
            s2 += g_pen[i];
        }
        sm1[tid] = s1;
        sm2[tid] = s2;
        __syncthreads();
#pragma unroll
        for (int stride = 128; stride; stride >>= 1) {
            if (tid < stride) {
                sm1[tid] += sm1[tid + stride];
                sm2[tid] += sm2[tid + stride];
            }
            __syncthreads();
        }
        if (tid == 0) {
            float logmse = sm1[0] / (float)NB;
            float viol   = sm2[0] / (float)NB;
            float total  = logmse + LAMB * viol;
            out[0] = total;
            if (out_size > 1) out[1] = logmse;
            if (out_size > 2) out[2] = viol;
            g_done = 0;   // reset for next graph replay
        }
    }
}

extern "C" void kernel_launch(void* const* d_in, const int* in_sizes, int n_in,
                              void* d_out, int out_size)
{
    const float* y_pred = (const float*)d_in[0];
    const float* y_true = (const float*)d_in[1];
    const float* Pmat   = (const float*)d_in[2];
    const float* params = (const float*)d_in[3];
    const float* Xs     = (const float*)d_in[4];

    cudaFuncSetAttribute(vil_main_kernel,
                         cudaFuncAttributeMaxDynamicSharedMemorySize, DSM_BYTES);
    vil_main_kernel<<<GRID, 256, DSM_BYTES>>>(y_pred, y_true, Pmat, params, Xs,
                                              (float*)d_out, out_size);
}

// round 10
// speedup vs baseline: 1.1509x; 1.1509x over previous
#include <cuda_runtime.h>

#define NB    2048
#define KD    256
#define PD    256
#define SD    10
#define PADS  12          // xst row stride in floats (10 used + 2 pad)
#define LAMB  0.5f
#define EPSF  1e-9f
#define NEG_PAD -1e30f

__device__ float    g_logmse[NB];
__device__ float    g_pen[NB];
__device__ unsigned g_done = 0;

typedef unsigned long long ull;

__device__ __forceinline__ ull ffma2(ull a, ull b, ull c) {
    ull d;
    asm("fma.rn.f32x2 %0, %1, %2, %3;" : "=l"(d) : "l"(a), "l"(b), "l"(c));
    return d;
}
__device__ __forceinline__ ull pack2(float x) {
    unsigned u = __float_as_uint(x);
    ull d;
    asm("mov.b64 %0, {%1, %2};" : "=l"(d) : "r"(u), "r"(u));
    return d;
}
__device__ __forceinline__ void unpack2(ull a, float& lo, float& hi) {
    unsigned l, h;
    asm("mov.b64 {%0, %1}, %2;" : "=r"(l), "=r"(h) : "l"(a));
    lo = __uint_as_float(l);
    hi = __uint_as_float(h);
}

// ---- top-R selection over this warp's s-slices; R = m+1 (compile-time) ----
template<int R>
__device__ __forceinline__ float sel_warp(const float* __restrict__ xh,
                                          const float* __restrict__ cph,
                                          int k, int jmax, int lane, int wl)
{
    float s_hm = 0.0f;
    for (int s = wl; s < SD; s += 4) {
        float t[R];
#pragma unroll
        for (int i = 0; i < R; ++i) t[i] = NEG_PAD;

        // candidates from X part
#pragma unroll
        for (int j = 0; j < 8; ++j) {
            int kk = lane + 32 * j;
            float v = (kk < k) ? fabsf(xh[kk * PADS + s]) : -1.0f;
#pragma unroll
            for (int i = R - 1; i >= 1; --i) t[i] = fmaxf(t[i], fminf(t[i - 1], v));
            t[0] = fmaxf(t[0], v);
        }
        // candidates from X@P part, trimmed to valid columns
        for (int j = 0; j < jmax; ++j) {
            float v = cph[s * PD + lane + 32 * j];
#pragma unroll
            for (int i = R - 1; i >= 1; --i) t[i] = fmaxf(t[i], fminf(t[i - 1], v));
            t[0] = fmaxf(t[0], v);
        }

        // butterfly merge of sorted top-R lists across 32 lanes
#pragma unroll
        for (int st = 0; st < 5; ++st) {
            float r[R], o[R];
#pragma unroll
            for (int i = 0; i < R; ++i)
                r[i] = __shfl_xor_sync(0xffffffffu, t[i], 1 << st);
#pragma unroll
            for (int j = 0; j < R; ++j) {
                float mx = fmaxf(t[j], r[j]);
#pragma unroll
                for (int i = 0; i < j; ++i)
                    mx = fmaxf(mx, fminf(t[i], r[j - 1 - i]));
                o[j] = mx;
            }
#pragma unroll
            for (int i = 0; i < R; ++i) t[i] = o[i];
        }

        s_hm = fmaxf(s_hm, t[0] / (t[R - 1] + EPSF));
    }
    return s_hm;
}

__global__ __launch_bounds__(128, 8)
void vil_main_kernel(const float* __restrict__ y_pred,
                     const float* __restrict__ y_true,
                     const float* __restrict__ Pmat,
                     const float* __restrict__ params,
                     const float* __restrict__ Xs,
                     float* __restrict__ out,
                     int out_size)
{
    __shared__ __align__(16) float xst[KD * PADS];   // X transposed+masked (12 KB)
    __shared__ __align__(16) float cp[SD * PD];      // masked |X@P|        (10 KB)
    __shared__ float warr[4];
    __shared__ unsigned is_last;

    const int b    = blockIdx.x;
    const int tid  = threadIdx.x;
    const int lane = tid & 31;
    const int wl   = tid >> 5;          // warp: 0..3

    int n = (int)params[b * 3 + 0];
    int k = (int)params[b * 3 + 1];
    int m = (int)params[b * 3 + 2];
    if (k > KD) k = KD;
    int pv = n - k;
    if (pv < 0) pv = 0;
    if (pv > PD) pv = PD;
    if (m < 0) m = 0;
    if (m > 8) m = 8;

    // ---- stage X transposed + masked into smem ----
    const float* Xb = Xs + (size_t)b * SD * KD;
    for (int i = tid; i < SD * KD; i += 128) {
        int s  = i >> 8;          // KD = 256
        int kk = i & (KD - 1);
        float v = Xb[i];
        xst[kk * PADS + s] = (kk < k) ? v : 0.0f;
    }
    __syncthreads();

    // ---- GEMM: thread owns 2 adjacent columns; per column 5 f32x2 s-pair accs.
    //      Threads with c0 >= pv skip: predicated-off LDGs fetch no sectors. ----
    const int c0 = tid << 1;
    const float* Pb = Pmat + (size_t)b * KD * PD + c0;

    ull a0 = 0ull, a1 = 0ull, a2 = 0ull, a3 = 0ull, a4 = 0ull;  // column c0
    ull b0 = 0ull, b1 = 0ull, b2 = 0ull, b3 = 0ull, b4 = 0ull;  // column c0+1

    if (c0 < pv) {
        float2 bufA[4], bufB[4];
#pragma unroll
        for (int u = 0; u < 4; ++u)
            bufA[u] = *reinterpret_cast<const float2*>(Pb + u * PD);
#pragma unroll
        for (int u = 0; u < 4; ++u)
            bufB[u] = *reinterpret_cast<const float2*>(Pb + (4 + u) * PD);

        for (int kk0 = 0; kk0 < KD; kk0 += 8) {
            const bool moreA = (kk0 + 8) < KD;
#pragma unroll
            for (int u = 0; u < 4; ++u) {
                const float2 pcur = bufA[u];
                if (moreA)
                    bufA[u] = *reinterpret_cast<const float2*>(Pb + (kk0 + 8 + u) * PD);
                const float* row = xst + (kk0 + u) * PADS;
                ulonglong2 q0 = *reinterpret_cast<const ulonglong2*>(row);      // s0..s3
                ulonglong2 q1 = *reinterpret_cast<const ulonglong2*>(row + 4);  // s4..s7
                ull x89       = *reinterpret_cast<const ull*>(row + 8);         // s8,s9
                ull pp0 = pack2(pcur.x);
                ull pp1 = pack2(pcur.y);
                a0 = ffma2(q0.x, pp0, a0);  b0 = ffma2(q0.x, pp1, b0);
                a1 = ffma2(q0.y, pp0, a1);  b1 = ffma2(q0.y, pp1, b1);
                a2 = ffma2(q1.x, pp0, a2);  b2 = ffma2(q1.x, pp1, b2);
                a3 = ffma2(q1.y, pp0, a3);  b3 = ffma2(q1.y, pp1, b3);
                a4 = ffma2(x89,  pp0, a4);  b4 = ffma2(x89,  pp1, b4);
            }
            const bool moreB = (kk0 + 12) < KD;
#pragma unroll
            for (int u = 0; u < 4; ++u) {
                const float2 pcur = bufB[u];
                if (moreB)
                    bufB[u] = *reinterpret_cast<const float2*>(Pb + (kk0 + 12 + u) * PD);
                const float* row = xst + (kk0 + 4 + u) * PADS;
                ulonglong2 q0 = *reinterpret_cast<const ulonglong2*>(row);
                ulonglong2 q1 = *reinterpret_cast<const ulonglong2*>(row + 4);
                ull x89       = *reinterpret_cast<const ull*>(row + 8);
                ull pp0 = pack2(pcur.x);
                ull pp1 = pack2(pcur.y);
                a0 = ffma2(q0.x, pp0, a0);  b0 = ffma2(q0.x, pp1, b0);
                a1 = ffma2(q0.y, pp0, a1);  b1 = ffma2(q0.y, pp1, b1);
                a2 = ffma2(q1.x, pp0, a2);  b2 = ffma2(q1.x, pp1, b2);
                a3 = ffma2(q1.y, pp0, a3);  b3 = ffma2(q1.y, pp1, b3);
                a4 = ffma2(x89,  pp0, a4);  b4 = ffma2(x89,  pp1, b4);
            }
        }
    }

    // ---- write masked |C| for both columns ----
    {
        float ca[SD], cb[SD];
        unpack2(a0, ca[0], ca[1]);  unpack2(b0, cb[0], cb[1]);
        unpack2(a1, ca[2], ca[3]);  unpack2(b1, cb[2], cb[3]);
        unpack2(a2, ca[4], ca[5]);  unpack2(b2, cb[4], cb[5]);
        unpack2(a3, ca[6], ca[7]);  unpack2(b3, cb[6], cb[7]);
        unpack2(a4, ca[8], ca[9]);  unpack2(b4, cb[8], cb[9]);
        const bool ok0 = c0 < pv;
        const bool ok1 = (c0 + 1) < pv;
#pragma unroll
        for (int s = 0; s < SD; ++s) {
            float2 w;
            w.x = ok0 ? fabsf(ca[s]) : -1.0f;
            w.y = ok1 ? fabsf(cb[s]) : -1.0f;
            *reinterpret_cast<float2*>(cp + s * PD + c0) = w;
        }
    }
    __syncthreads();

    // ---- selection, templated on R = m+1 (m is CTA-uniform) ----
    const int jmax = (pv + 31) >> 5;
    float s_hm;
    switch (m) {
        case 0: s_hm = sel_warp<1>(xst, cp, k, jmax, lane, wl); break;
        case 1: s_hm = sel_warp<2>(xst, cp, k, jmax, lane, wl); break;
        case 2: s_hm = sel_warp<3>(xst, cp, k, jmax, lane, wl); break;
        case 3: s_hm = sel_warp<4>(xst, cp, k, jmax, lane, wl); break;
        case 4: s_hm = sel_warp<5>(xst, cp, k, jmax, lane, wl); break;
        case 5: s_hm = sel_warp<6>(xst, cp, k, jmax, lane, wl); break;
        case 6: s_hm = sel_warp<7>(xst, cp, k, jmax, lane, wl); break;
        case 7: s_hm = sel_warp<8>(xst, cp, k, jmax, lane, wl); break;
        default: s_hm = sel_warp<9>(xst, cp, k, jmax, lane, wl); break;
    }
    if (lane == 0) warr[wl] = s_hm;
    __syncthreads();

    // ---- per-batch scalar outputs ----
    if (tid == 0) {
        float mh = fmaxf(fmaxf(warr[0], warr[1]), fmaxf(warr[2], warr[3]));
        float yp = y_pred[b];
        float lt = log2f(fmaxf(y_true[b], EPSF));
        float lp = log2f(fmaxf(yp, EPSF));
        float d  = lt - lp;
        g_logmse[b] = d * d;
        bool valid  = (m + 1) <= n;
        g_pen[b]    = valid ? fmaxf(mh - yp, 0.0f) : 0.0f;
        __threadfence();
        unsigned prev = atomicAdd(&g_done, 1u);
        is_last = (prev == NB - 1) ? 1u : 0u;
    }
    __syncthreads();

    // ---- last block performs the deterministic final reduction ----
    if (is_last) {
        __threadfence();   // acquire: make all blocks' g_ writes visible
        __shared__ float sm1[128];
        __shared__ float sm2[128];
        float s1 = 0.0f, s2 = 0.0f;
        for (int i = tid; i < NB; i += 128) {   // fixed order -> deterministic
            s1 += g_logmse[i];
            s2 += g_pen[i];
        }
        sm1[tid] = s1;
        sm2[tid] = s2;
        __syncthreads();
#pragma unroll
        for (int stride = 64; stride; stride >>= 1) {
            if (tid < stride) {
                sm1[tid] += sm1[tid + stride];
                sm2[tid] += sm2[tid + stride];
            }
            __syncthreads();
        }
        if (tid == 0) {
            float logmse = sm1[0] / (float)NB;
            float viol   = sm2[0] / (float)NB;
            float total  = logmse + LAMB * viol;
            out[0] = total;
            if (out_size > 1) out[1] = logmse;
            if (out_size > 2) out[2] = viol;
            g_done = 0;   // reset for next graph replay
        }
    }
}

extern "C" void kernel_launch(void* const* d_in, const int* in_sizes, int n_in,
                              void* d_out, int out_size)
{
    const float* y_pred = (const float*)d_in[0];
    const float* y_true = (const float*)d_in[1];
    const float* Pmat   = (const float*)d_in[2];
    const float* params = (const float*)d_in[3];
    const float* Xs     = (const float*)d_in[4];

    vil_main_kernel<<<NB, 128>>>(y_pred, y_true, Pmat, params, Xs,
                                 (float*)d_out, out_size);
}